// round 8
// baseline (speedup 1.0000x reference)
#include <cuda_runtime.h>

#define NB   32768
#define PP   32
#define NCC  33
#define CEBLK 256   // CE kernel: 256 blocks x 256 threads (128 items x 2 sides)
#define CHBLK 512   // chamfer kernel: 2 sides x 256 item-blocks, 128 thr

__device__ float g_ch_partials[CHBLK];
__device__ float g_ce_partials[CEBLK];
__device__ int   g_predn[2 * NB];    // predicted counts: [side*NB + b]
__device__ int   g_count;            // zero-init; reset each launch by finisher

typedef unsigned long long ull;

__device__ __forceinline__ ull ffma2(ull a, ull b, ull c) {
    ull d; asm("fma.rn.f32x2 %0, %1, %2, %3;" : "=l"(d) : "l"(a), "l"(b), "l"(c)); return d;
}
__device__ __forceinline__ ull fadd2(ull a, ull b) {
    ull d; asm("add.rn.f32x2 %0, %1, %2;" : "=l"(d) : "l"(a), "l"(b)); return d;
}
__device__ __forceinline__ ull fmul2(ull a, ull b) {
    ull d; asm("mul.rn.f32x2 %0, %1, %2;" : "=l"(d) : "l"(a), "l"(b)); return d;
}
__device__ __forceinline__ ull pack2(float lo, float hi) {
    ull d; asm("mov.b64 %0, {%1, %2};" : "=l"(d) : "f"(lo), "f"(hi)); return d;
}
__device__ __forceinline__ float2 unpack2(ull v) {
    float2 r; asm("mov.b64 {%0, %1}, %2;" : "=f"(r.x), "=f"(r.y) : "l"(v)); return r;
}

// ============================ Kernel 1: CE ============================
// 256 blocks x 256 threads. Each block: 128 items. Thread t handles
// (item = t>>1, side = t&1). Computes 5*CE partial sum and pred counts.
__global__ __launch_bounds__(256)
void ce_kernel(const float* __restrict__ pole_logits,
               const float* __restrict__ zero_logits,
               const int*   __restrict__ tnp,
               const int*   __restrict__ tnz) {
    __shared__ __align__(16) float slog[2][128 * NCC];   // 33792 B
    __shared__ float sred[256];

    const int tid  = threadIdx.x;
    const int ib   = blockIdx.x;
    const int item = tid >> 1;
    const int side = tid & 1;
    const int b    = ib * 128 + item;

    // Coalesced float4 staging of both logit slabs (1056 float4 each).
    {
        const float4* s0 = (const float4*)(pole_logits + (size_t)ib * 128 * NCC);
        const float4* s1 = (const float4*)(zero_logits + (size_t)ib * 128 * NCC);
        float4* d0 = (float4*)slog[0];
        float4* d1 = (float4*)slog[1];
#pragma unroll
        for (int k = 0; k < 4; k++) {
            d0[tid + 256 * k] = __ldg(s0 + tid + 256 * k);
            d1[tid + 256 * k] = __ldg(s1 + tid + 256 * k);
        }
        if (tid < 32) {
            d0[1024 + tid] = __ldg(s0 + 1024 + tid);
            d1[1024 + tid] = __ldg(s1 + 1024 + tid);
        }
    }
    __syncthreads();

    const float* row = &slog[side][item * NCC];
    const int tgt = side ? __ldg(tnz + b) : __ldg(tnp + b);

    float m = -1e30f; int amax = 0;
#pragma unroll
    for (int j = 0; j < NCC; j++) {
        float x = row[j];
        if (x > m) { m = x; amax = j; }
    }
    float s = 0.f;
#pragma unroll
    for (int j = 0; j < NCC; j++)
        s += __expf(row[j] - m);
    const float ce = m + __logf(s) - row[tgt];

    g_predn[side * NB + b] = amax;

    // Deterministic tree reduction of 5*ce over 256 threads.
    sred[tid] = 5.f * ce;
    __syncthreads();
#pragma unroll
    for (int st = 128; st > 0; st >>= 1) {
        if (tid < st) sred[tid] += sred[tid + st];
        __syncthreads();
    }
    if (tid == 0) g_ce_partials[ib] = sred[0];
}

// ========================== Kernel 2: chamfer ==========================

// Two pred points (one float4) vs all 16 packed target pairs.
__device__ __forceinline__ void pair_body(float4 p, int i, int np,
                                          const ull* __restrict__ TX,
                                          const ull* __restrict__ TY,
                                          float* __restrict__ mintlo,
                                          float* __restrict__ minthi,
                                          float& sum_minp, float& sum_psq) {
    const bool va = (2 * i < np), vb = (2 * i + 1 < np);
    float ax = p.x, ay = p.y, bx = p.z, by = p.w;
    if (va) sum_psq += ax * ax + ay * ay; else { ax = -1e18f; ay = -1e18f; }
    if (vb) sum_psq += bx * bx + by * by; else { bx = -1e18f; by = -1e18f; }

    const ull AX = pack2(ax, ax), AY = pack2(ay, ay);
    const ull BX = pack2(bx, bx), BY = pack2(by, by);

    float mina = 1e30f, minb = 1e30f;
#pragma unroll
    for (int j = 0; j < PP / 2; j++) {
        ull dxa = fadd2(AX, TX[j]);
        ull dya = fadd2(AY, TY[j]);
        ull da  = ffma2(dxa, dxa, fmul2(dya, dya));
        ull dxb = fadd2(BX, TX[j]);
        ull dyb = fadd2(BY, TY[j]);
        ull db  = ffma2(dxb, dxb, fmul2(dyb, dyb));
        float2 daf = unpack2(da), dbf = unpack2(db);
        mina = fminf(mina, fminf(daf.x, daf.y));
        minb = fminf(minb, fminf(dbf.x, dbf.y));
        mintlo[j] = fminf(mintlo[j], fminf(daf.x, dbf.x));
        minthi[j] = fminf(minthi[j], fminf(daf.y, dbf.y));
    }
    if (va) sum_minp += mina;
    if (vb) sum_minp += minb;
}

__device__ __forceinline__ float chamfer(const float4* __restrict__ pred4,
                                         const float4* __restrict__ tgt4,
                                         int np, int nt) {
    // Targets (negated, packed); invalid -> -(+1e18). 16 batched LDG.128.
    ull TX[PP / 2], TY[PP / 2];
    float sum_tsq = 0.f;
#pragma unroll
    for (int j = 0; j < PP / 2; j++) {
        float4 t = __ldg(tgt4 + j);
        float x0, y0, x1, y1;
        if (2 * j < nt)     { sum_tsq += t.x * t.x + t.y * t.y; x0 = -t.x; y0 = -t.y; }
        else                { x0 = -1e18f; y0 = -1e18f; }
        if (2 * j + 1 < nt) { sum_tsq += t.z * t.z + t.w * t.w; x1 = -t.z; y1 = -t.w; }
        else                { x1 = -1e18f; y1 = -1e18f; }
        TX[j] = pack2(x0, x1); TY[j] = pack2(y0, y1);
    }

    float mintlo[PP / 2], minthi[PP / 2];
#pragma unroll
    for (int j = 0; j < PP / 2; j++) { mintlo[j] = 1e30f; minthi[j] = 1e30f; }

    float sum_minp = 0.f, sum_psq = 0.f;

    // Stream preds: chunk = 2 float4 with one-chunk lookahead.
    float4 c0 = __ldg(pred4 + 0);
    float4 c1 = __ldg(pred4 + 1);
#pragma unroll 1
    for (int c = 0; c < 8; c++) {
        float4 n0, n1;
        if (c < 7) {
            n0 = __ldg(pred4 + 2 * c + 2);
            n1 = __ldg(pred4 + 2 * c + 3);
        }
        pair_body(c0, 2 * c + 0, np, TX, TY, mintlo, minthi, sum_minp, sum_psq);
        pair_body(c1, 2 * c + 1, np, TX, TY, mintlo, minthi, sum_minp, sum_psq);
        c0 = n0; c1 = n1;
    }

    float sum_mint = 0.f;
#pragma unroll
    for (int j = 0; j < PP / 2; j++) {
        if (2 * j < nt)     sum_mint += mintlo[j];
        if (2 * j + 1 < nt) sum_mint += minthi[j];
    }

    if (np == 0 && nt == 0) return 0.f;
    if (np == 0) return sum_tsq;
    if (nt == 0) return sum_psq;
    return sum_minp / (float)np + sum_mint / (float)nt;
}

__global__ __launch_bounds__(128, 4)
void chamfer_kernel(const float4* __restrict__ poles,
                    const float4* __restrict__ zeros,
                    const float4* __restrict__ tpoles,
                    const float4* __restrict__ tzeros,
                    const int*    __restrict__ tnp,
                    const int*    __restrict__ tnz,
                    float*        __restrict__ out) {
    __shared__ float sred[128];
    __shared__ int   sflag;

    const int tid  = threadIdx.x;
    const int side = blockIdx.x & 1;
    const int ib   = blockIdx.x >> 1;
    const int b    = ib * 128 + tid;

    const float4* pred = side ? zeros  : poles;
    const float4* tgt  = side ? tzeros : tpoles;
    const int*    tn   = side ? tnz    : tnp;

    if (tid == 0) sflag = 0;

    const int nt = __ldg(tn + b);
    const int np = g_predn[side * NB + b];
    const float ch = chamfer(pred + (size_t)b * (PP / 2),
                             tgt  + (size_t)b * (PP / 2), np, nt);

    // Deterministic block tree reduction
    sred[tid] = ch;
    __syncthreads();
#pragma unroll
    for (int s = 64; s > 0; s >>= 1) {
        if (tid < s) sred[tid] += sred[tid + s];
        __syncthreads();
    }

    if (tid == 0) {
        g_ch_partials[blockIdx.x] = sred[0];
        __threadfence();
        unsigned n = atomicAdd(&g_count, 1);
        if (n == CHBLK - 1) sflag = 1;
    }
    __syncthreads();

    // Last block: deterministic fixed-order tree over chamfer + CE partials.
    if (sflag) {
        __threadfence();
        volatile float* vch = g_ch_partials;
        volatile float* vce = g_ce_partials;
        sred[tid] = ((vch[tid] + vch[tid + 128]) + (vch[tid + 256] + vch[tid + 384]))
                  + (vce[tid] + vce[tid + 128]);
        __syncthreads();
#pragma unroll
        for (int s = 64; s > 0; s >>= 1) {
            if (tid < s) sred[tid] += sred[tid + s];
            __syncthreads();
        }
        if (tid == 0) {
            out[0] = sred[0] * (1.0f / (float)NB);
            g_count = 0;   // reset for next graph replay
        }
    }
}

extern "C" void kernel_launch(void* const* d_in, const int* in_sizes, int n_in,
                              void* d_out, int out_size) {
    const float*  pole_logits = (const float*)d_in[0];
    const float*  zero_logits = (const float*)d_in[1];
    const float4* poles       = (const float4*)d_in[2];
    const float4* zeros       = (const float4*)d_in[3];
    const float4* tpoles      = (const float4*)d_in[4];
    const float4* tzeros      = (const float4*)d_in[5];
    const int*    tnp         = (const int*)d_in[6];
    const int*    tnz         = (const int*)d_in[7];

    ce_kernel<<<CEBLK, 256>>>(pole_logits, zero_logits, tnp, tnz);
    chamfer_kernel<<<CHBLK, 128>>>(poles, zeros, tpoles, tzeros,
                                   tnp, tnz, (float*)d_out);
}

// round 9
// speedup vs baseline: 1.1747x; 1.1747x over previous
#include <cuda_runtime.h>

#define NB    32768
#define PP    32
#define NCC   33
#define CEBLK 256    // CE kernel: 256 blocks x 256 threads
#define CHBLK 2048   // chamfer: 2 sides x 1024 blocks, 128 thr, 32 items/block

__device__ float g_ch_partials[CHBLK];
__device__ float g_ce_partials[CEBLK];
__device__ int   g_predn[2 * NB];    // predicted counts: [side*NB + b]
__device__ int   g_count;            // zero-init; reset each launch by finisher

typedef unsigned long long ull;

__device__ __forceinline__ ull ffma2(ull a, ull b, ull c) {
    ull d; asm("fma.rn.f32x2 %0, %1, %2, %3;" : "=l"(d) : "l"(a), "l"(b), "l"(c)); return d;
}
__device__ __forceinline__ ull fadd2(ull a, ull b) {
    ull d; asm("add.rn.f32x2 %0, %1, %2;" : "=l"(d) : "l"(a), "l"(b)); return d;
}
__device__ __forceinline__ ull fmul2(ull a, ull b) {
    ull d; asm("mul.rn.f32x2 %0, %1, %2;" : "=l"(d) : "l"(a), "l"(b)); return d;
}
__device__ __forceinline__ ull pack2(float lo, float hi) {
    ull d; asm("mov.b64 %0, {%1, %2};" : "=l"(d) : "f"(lo), "f"(hi)); return d;
}
__device__ __forceinline__ float2 unpack2(ull v) {
    float2 r; asm("mov.b64 {%0, %1}, %2;" : "=f"(r.x), "=f"(r.y) : "l"(v)); return r;
}

// ============================ Kernel 1: CE ============================
__global__ __launch_bounds__(256)
void ce_kernel(const float* __restrict__ pole_logits,
               const float* __restrict__ zero_logits,
               const int*   __restrict__ tnp,
               const int*   __restrict__ tnz) {
    __shared__ __align__(16) float slog[2][128 * NCC];   // 33792 B
    __shared__ float sred[256];

    const int tid  = threadIdx.x;
    const int ib   = blockIdx.x;
    const int item = tid >> 1;
    const int side = tid & 1;
    const int b    = ib * 128 + item;

    {
        const float4* s0 = (const float4*)(pole_logits + (size_t)ib * 128 * NCC);
        const float4* s1 = (const float4*)(zero_logits + (size_t)ib * 128 * NCC);
        float4* d0 = (float4*)slog[0];
        float4* d1 = (float4*)slog[1];
#pragma unroll
        for (int k = 0; k < 4; k++) {
            d0[tid + 256 * k] = __ldg(s0 + tid + 256 * k);
            d1[tid + 256 * k] = __ldg(s1 + tid + 256 * k);
        }
        if (tid < 32) {
            d0[1024 + tid] = __ldg(s0 + 1024 + tid);
            d1[1024 + tid] = __ldg(s1 + 1024 + tid);
        }
    }
    __syncthreads();

    const float* row = &slog[side][item * NCC];
    const int tgt = side ? __ldg(tnz + b) : __ldg(tnp + b);

    float m = -1e30f; int amax = 0;
#pragma unroll
    for (int j = 0; j < NCC; j++) {
        float x = row[j];
        if (x > m) { m = x; amax = j; }
    }
    float s = 0.f;
#pragma unroll
    for (int j = 0; j < NCC; j++)
        s += __expf(row[j] - m);
    const float ce = m + __logf(s) - row[tgt];

    g_predn[side * NB + b] = amax;

    sred[tid] = 5.f * ce;
    __syncthreads();
#pragma unroll
    for (int st = 128; st > 0; st >>= 1) {
        if (tid < st) sred[tid] += sred[tid + st];
        __syncthreads();
    }
    if (tid == 0) g_ce_partials[ib] = sred[0];
}

// ========================== Kernel 2: chamfer ==========================
// Item split across a 4-lane group: lane q owns targets [8q, 8q+8) resident
// in registers; all 4 lanes stream the full 32 preds (broadcast loads).

__device__ __forceinline__ void pair_body4(float4 p, int i, int np,
                                           const ull* __restrict__ TX,
                                           const ull* __restrict__ TY,
                                           float* __restrict__ mintlo,
                                           float* __restrict__ minthi,
                                           float& sum_minp, float& sum_psq) {
    const bool va = (2 * i < np), vb = (2 * i + 1 < np);
    float ax = p.x, ay = p.y, bx = p.z, by = p.w;
    if (va) sum_psq += ax * ax + ay * ay; else { ax = -1e18f; ay = -1e18f; }
    if (vb) sum_psq += bx * bx + by * by; else { bx = -1e18f; by = -1e18f; }

    const ull AX = pack2(ax, ax), AY = pack2(ay, ay);
    const ull BX = pack2(bx, bx), BY = pack2(by, by);

    float mina = 1e30f, minb = 1e30f;
#pragma unroll
    for (int j = 0; j < 4; j++) {
        ull dxa = fadd2(AX, TX[j]);
        ull dya = fadd2(AY, TY[j]);
        ull da  = ffma2(dxa, dxa, fmul2(dya, dya));
        ull dxb = fadd2(BX, TX[j]);
        ull dyb = fadd2(BY, TY[j]);
        ull db  = ffma2(dxb, dxb, fmul2(dyb, dyb));
        float2 daf = unpack2(da), dbf = unpack2(db);
        mina = fminf(mina, fminf(daf.x, daf.y));
        minb = fminf(minb, fminf(dbf.x, dbf.y));
        mintlo[j] = fminf(mintlo[j], fminf(daf.x, dbf.x));
        minthi[j] = fminf(minthi[j], fminf(daf.y, dbf.y));
    }
    // Complete min over all 32 targets across the 4-lane group (exact).
    mina = fminf(mina, __shfl_xor_sync(0xFFFFFFFFu, mina, 1));
    mina = fminf(mina, __shfl_xor_sync(0xFFFFFFFFu, mina, 2));
    minb = fminf(minb, __shfl_xor_sync(0xFFFFFFFFu, minb, 1));
    minb = fminf(minb, __shfl_xor_sync(0xFFFFFFFFu, minb, 2));
    if (va) sum_minp += mina;
    if (vb) sum_minp += minb;
}

__global__ __launch_bounds__(128, 6)
void chamfer_kernel(const float4* __restrict__ poles,
                    const float4* __restrict__ zeros,
                    const float4* __restrict__ tpoles,
                    const float4* __restrict__ tzeros,
                    const int*    __restrict__ tnp,
                    const int*    __restrict__ tnz,
                    float*        __restrict__ out) {
    __shared__ float sred[128];
    __shared__ int   sflag;

    const int tid  = threadIdx.x;
    const int side = blockIdx.x & 1;
    const int ib   = blockIdx.x >> 1;
    const int q    = tid & 3;           // lane within 4-group
    const int item = tid >> 2;          // 0..31
    const int b    = ib * 32 + item;

    const float4* pred = (side ? zeros  : poles)  + (size_t)b * (PP / 2);
    const float4* tgt  = (side ? tzeros : tpoles) + (size_t)b * (PP / 2);
    const int*    tn   = side ? tnz : tnp;

    if (tid == 0) sflag = 0;

    const int nt = __ldg(tn + b);
    const int np = g_predn[side * NB + b];

    // This lane's 8 targets (negated, packed); invalid -> stored -1e18.
    ull TX[4], TY[4];
    float sum_tsq_loc = 0.f;
#pragma unroll
    for (int j = 0; j < 4; j++) {
        float4 t = __ldg(tgt + 4 * q + j);
        const int g = 8 * q + 2 * j;
        float x0, y0, x1, y1;
        if (g < nt)     { sum_tsq_loc += t.x * t.x + t.y * t.y; x0 = -t.x; y0 = -t.y; }
        else            { x0 = -1e18f; y0 = -1e18f; }
        if (g + 1 < nt) { sum_tsq_loc += t.z * t.z + t.w * t.w; x1 = -t.z; y1 = -t.w; }
        else            { x1 = -1e18f; y1 = -1e18f; }
        TX[j] = pack2(x0, x1); TY[j] = pack2(y0, y1);
    }

    float mintlo[4], minthi[4];
#pragma unroll
    for (int j = 0; j < 4; j++) { mintlo[j] = 1e30f; minthi[j] = 1e30f; }

    float sum_minp = 0.f, sum_psq = 0.f;

    // Stream all 32 preds: chunk = 2 float4 with one-chunk lookahead.
    float4 c0 = __ldg(pred + 0);
    float4 c1 = __ldg(pred + 1);
#pragma unroll 1
    for (int c = 0; c < 8; c++) {
        float4 n0, n1;
        if (c < 7) {
            n0 = __ldg(pred + 2 * c + 2);
            n1 = __ldg(pred + 2 * c + 3);
        }
        pair_body4(c0, 2 * c + 0, np, TX, TY, mintlo, minthi, sum_minp, sum_psq);
        pair_body4(c1, 2 * c + 1, np, TX, TY, mintlo, minthi, sum_minp, sum_psq);
        c0 = n0; c1 = n1;
    }

    float sum_mint_loc = 0.f;
#pragma unroll
    for (int j = 0; j < 4; j++) {
        const int g = 8 * q + 2 * j;
        if (g < nt)     sum_mint_loc += mintlo[j];
        if (g + 1 < nt) sum_mint_loc += minthi[j];
    }
    // Combine the 4 lanes' target-side partials (fixed butterfly order).
    float sum_mint = sum_mint_loc + __shfl_xor_sync(0xFFFFFFFFu, sum_mint_loc, 1);
    sum_mint      += __shfl_xor_sync(0xFFFFFFFFu, sum_mint, 2);
    float sum_tsq  = sum_tsq_loc + __shfl_xor_sync(0xFFFFFFFFu, sum_tsq_loc, 1);
    sum_tsq       += __shfl_xor_sync(0xFFFFFFFFu, sum_tsq, 2);

    float ch;
    if (np == 0 && nt == 0) ch = 0.f;
    else if (np == 0)       ch = sum_tsq;
    else if (nt == 0)       ch = sum_psq;
    else                    ch = sum_minp / (float)np + sum_mint / (float)nt;

    float acc = (q == 0) ? ch : 0.f;   // count each item once

    // Deterministic block tree reduction
    sred[tid] = acc;
    __syncthreads();
#pragma unroll
    for (int s = 64; s > 0; s >>= 1) {
        if (tid < s) sred[tid] += sred[tid + s];
        __syncthreads();
    }

    if (tid == 0) {
        g_ch_partials[blockIdx.x] = sred[0];
        __threadfence();
        unsigned n = atomicAdd(&g_count, 1);
        if (n == CHBLK - 1) sflag = 1;
    }
    __syncthreads();

    // Last block: deterministic fixed-order sum over all partials.
    if (sflag) {
        __threadfence();
        volatile float* vch = g_ch_partials;
        volatile float* vce = g_ce_partials;
        float t = 0.f;
#pragma unroll
        for (int k = 0; k < CHBLK / 128; k++)
            t += vch[tid + 128 * k];
        t += vce[tid];
        t += vce[tid + 128];
        sred[tid] = t;
        __syncthreads();
#pragma unroll
        for (int s = 64; s > 0; s >>= 1) {
            if (tid < s) sred[tid] += sred[tid + s];
            __syncthreads();
        }
        if (tid == 0) {
            out[0] = sred[0] * (1.0f / (float)NB);
            g_count = 0;   // reset for next graph replay
        }
    }
}

extern "C" void kernel_launch(void* const* d_in, const int* in_sizes, int n_in,
                              void* d_out, int out_size) {
    const float*  pole_logits = (const float*)d_in[0];
    const float*  zero_logits = (const float*)d_in[1];
    const float4* poles       = (const float4*)d_in[2];
    const float4* zeros       = (const float4*)d_in[3];
    const float4* tpoles      = (const float4*)d_in[4];
    const float4* tzeros      = (const float4*)d_in[5];
    const int*    tnp         = (const int*)d_in[6];
    const int*    tnz         = (const int*)d_in[7];

    ce_kernel<<<CEBLK, 256>>>(pole_logits, zero_logits, tnp, tnz);
    chamfer_kernel<<<CHBLK, 128>>>(poles, zeros, tpoles, tzeros,
                                   tnp, tnz, (float*)d_out);
}